// round 4
// baseline (speedup 1.0000x reference)
#include <cuda_runtime.h>
#include <cstdint>

// Problem constants: N=100000, F=512, H=16, C=40, E=3200000
#define NMAX 100000
#define EMAX 3200000
#define FDIM 512
#define HDIM 16
#define CDIM 40

// ---- scratch (static device globals; no allocation allowed) ----
__device__ int    g_is64;
__device__ int    g_deg[NMAX];
__device__ int    g_rowptr[NMAX];
__device__ int    g_cursor[NMAX];
__device__ float  g_dinv[NMAX];
__device__ int    g_csr[EMAX];        // src ids grouped by dst
__device__ float4 g_h [NMAX * 4];     // dinv-scaled hidden layer 1 (gather table)
__device__ float4 g_h2[NMAX * 4];     // dinv-scaled hidden layer 2 (gather table)

// ---- f32x2 packed-math helpers (sm_103a) ----
__device__ __forceinline__ unsigned long long f2_fma(
    unsigned long long a, unsigned long long b, unsigned long long c) {
    unsigned long long d;
    asm("fma.rn.f32x2 %0, %1, %2, %3;" : "=l"(d) : "l"(a), "l"(b), "l"(c));
    return d;
}
__device__ __forceinline__ unsigned long long f2_add(
    unsigned long long a, unsigned long long b) {
    unsigned long long d;
    asm("add.rn.f32x2 %0, %1, %2;" : "=l"(d) : "l"(a), "l"(b));
    return d;
}
__device__ __forceinline__ unsigned long long f2_mul(
    unsigned long long a, unsigned long long b) {
    unsigned long long d;
    asm("mul.rn.f32x2 %0, %1, %2;" : "=l"(d) : "l"(a), "l"(b));
    return d;
}
__device__ __forceinline__ unsigned long long f2_pack(float lo, float hi) {
    unsigned long long d;
    asm("mov.b64 %0, {%1, %2};" : "=l"(d) : "f"(lo), "f"(hi));
    return d;
}

// ---------------------------------------------------------------
// Zero degree; thread 0 detects int64 vs int32 edge buffer (odd 32-bit
// words of small nonneg int64 ids are all zero).
__global__ void k_init(const int* __restrict__ ei, int N) {
    int i = blockIdx.x * blockDim.x + threadIdx.x;
    if (i < N) g_deg[i] = 0;
    if (i == 0) {
        int any = 0;
        #pragma unroll
        for (int q = 1; q < 256; q += 2) any |= ei[q];
        g_is64 = (any == 0) ? 1 : 0;
    }
}

__device__ __forceinline__ int dec_src(const void* ei, int E, int e) {
    return g_is64 ? (int)((const long long*)ei)[e] : ((const int*)ei)[e];
}
__device__ __forceinline__ int dec_dst(const void* ei, int E, int e) {
    return g_is64 ? (int)((const long long*)ei)[(size_t)E + e]
                  : ((const int*)ei)[E + e];
}

__global__ __launch_bounds__(256) void k_deg(const void* __restrict__ ei, int E) {
    int e = blockIdx.x * blockDim.x + threadIdx.x;
    if (e >= E) return;
    atomicAdd(&g_deg[dec_dst(ei, E, e)], 1);
}

// Single-block exclusive scan of g_deg -> g_rowptr (+ cursor copy).
__global__ __launch_bounds__(1024) void k_scan(int N) {
    __shared__ int part[1024];
    int t = threadIdx.x;
    int chunk = (N + 1023) / 1024;
    int base = t * chunk;
    int s = 0;
    for (int q = 0; q < chunk; q++) {
        int i = base + q;
        if (i < N) s += g_deg[i];
    }
    part[t] = s;
    __syncthreads();
    for (int off = 1; off < 1024; off <<= 1) {
        int v = (t >= off) ? part[t - off] : 0;
        __syncthreads();
        part[t] += v;
        __syncthreads();
    }
    int excl = (t == 0) ? 0 : part[t - 1];
    for (int q = 0; q < chunk; q++) {
        int i = base + q;
        if (i < N) {
            g_rowptr[i] = excl;
            g_cursor[i] = excl;
            excl += g_deg[i];
        }
    }
}

__global__ void k_dinv(int N) {
    int i = blockIdx.x * blockDim.x + threadIdx.x;
    if (i < N) g_dinv[i] = rsqrtf((float)(g_deg[i] + 1));  // +1 self-loop
}

__global__ __launch_bounds__(256) void k_fill(const void* __restrict__ ei, int E) {
    int e = blockIdx.x * blockDim.x + threadIdx.x;
    if (e >= E) return;
    int s = dec_src(ei, E, e);
    int d = dec_dst(ei, E, e);
    int pos = atomicAdd(&g_cursor[d], 1);
    g_csr[pos] = s;
}

// ---------------------------------------------------------------
// GEMM1 + scale:  g_h[i,:] = dinv[i] * (x[i,:] @ W1)
// Warp computes 4 rows; x loaded as float4 (k = 4*lane + 128*i + q).
// W1 staged in shared lane-major: wS[((j2*4+i)*4+q)*32 + lane] so the
// inner LDS.64 is lane-contiguous (conflict-free). f32x2 accumulators;
// value-halving butterfly reduction tail.
__global__ __launch_bounds__(256, 2) void k_gemm1(
    const float* __restrict__ x, const float* __restrict__ W1, int N)
{
    __shared__ unsigned long long wS[4096];
    {
        const unsigned long long* gw = (const unsigned long long*)W1;
        for (int idx = threadIdx.x; idx < 4096; idx += 256) {
            int lane_ = idx & 31;
            int q  = (idx >> 5) & 3;
            int i  = (idx >> 7) & 3;
            int j2 = idx >> 9;
            int k = 4 * lane_ + 128 * i + q;
            wS[idx] = gw[k * 8 + j2];
        }
    }
    __syncthreads();

    int warp = threadIdx.x >> 5;
    int lane = threadIdx.x & 31;
    int r0 = blockIdx.x * 32 + warp * 4;

    unsigned long long acc[4][8];
    #pragma unroll
    for (int r = 0; r < 4; r++)
        #pragma unroll
        for (int j = 0; j < 8; j++) acc[r][j] = 0ull;

    bool vr[4];
    const float4* xp[4];
    #pragma unroll
    for (int r = 0; r < 4; r++) {
        vr[r] = (r0 + r) < N;
        xp[r] = (const float4*)(x + (size_t)(vr[r] ? (r0 + r) : 0) * FDIM);
    }

    #pragma unroll
    for (int i = 0; i < 4; i++) {
        float4 xv[4];
        #pragma unroll
        for (int r = 0; r < 4; r++) {
            float4 t = xp[r][lane + 32 * i];
            xv[r].x = vr[r] ? t.x : 0.0f;
            xv[r].y = vr[r] ? t.y : 0.0f;
            xv[r].z = vr[r] ? t.z : 0.0f;
            xv[r].w = vr[r] ? t.w : 0.0f;
        }
        #pragma unroll
        for (int q = 0; q < 4; q++) {
            unsigned long long pr[4];
            #pragma unroll
            for (int r = 0; r < 4; r++) {
                float c = (q == 0) ? xv[r].x : (q == 1) ? xv[r].y
                        : (q == 2) ? xv[r].z : xv[r].w;
                pr[r] = f2_pack(c, c);
            }
            #pragma unroll
            for (int j = 0; j < 8; j++) {
                unsigned long long wv = wS[((j * 4 + i) * 4 + q) * 32 + lane];
                acc[0][j] = f2_fma(pr[0], wv, acc[0][j]);
                acc[1][j] = f2_fma(pr[1], wv, acc[1][j]);
                acc[2][j] = f2_fma(pr[2], wv, acc[2][j]);
                acc[3][j] = f2_fma(pr[3], wv, acc[3][j]);
            }
        }
    }

    // value-halving butterfly: 32 packed values -> 1 per lane
    unsigned long long v[32];
    #pragma unroll
    for (int r = 0; r < 4; r++)
        #pragma unroll
        for (int j = 0; j < 8; j++) v[r * 8 + j] = acc[r][j];

    #pragma unroll
    for (int s = 0; s < 5; s++) {
        const int m = 1 << s;
        const int half = 16 >> s;
        bool up = (lane & m) != 0;
        #pragma unroll
        for (int q = 0; q < 16; q++) {
            if (q < half) {
                unsigned long long keep = up ? v[q + half] : v[q];
                unsigned long long mine = up ? v[q] : v[q + half];
                unsigned long long got = __shfl_xor_sync(0xffffffffu, mine, m);
                v[q] = f2_add(keep, got);
            }
        }
    }

    int p = ((lane & 1) << 4) | ((lane & 2) << 2) | (lane & 4) |
            ((lane & 8) >> 2) | ((lane & 16) >> 4);
    int r = p >> 3, j2 = p & 7;
    int row = r0 + r;
    if (row < N) {
        float dv = g_dinv[row];
        unsigned long long res = f2_mul(v[0], f2_pack(dv, dv));
        ((unsigned long long*)g_h)[(size_t)row * 8 + j2] = res;
    }
}

// ---------------------------------------------------------------
// Pull-prop layer 1 + mid epilogue. One warp per dst node.
// Lane = (grp=lane>>2, c=lane&3): grp indexes source within a chunk of
// 8, c indexes the float4 chunk. Cross-group reduce via xor-butterfly.
// h2[d] = dinv * relu(dinv*(sum + self) + b1)
__global__ __launch_bounds__(256) void k_prop1(const float* __restrict__ b1, int N) {
    int wg = (blockIdx.x * 256 + threadIdx.x) >> 5;
    if (wg >= N) return;
    int lane = threadIdx.x & 31;
    int c = lane & 3, grp = lane >> 2;
    int d = wg;
    int start = g_rowptr[d];
    int cnt = g_deg[d];

    float4 a0 = make_float4(0.f, 0.f, 0.f, 0.f);
    float4 a1 = make_float4(0.f, 0.f, 0.f, 0.f);
    for (int base = 0; base < cnt; base += 16) {
        int i0 = base + grp, i1 = base + 8 + grp;
        if (i0 < cnt) {
            float4 v = g_h[(size_t)g_csr[start + i0] * 4 + c];
            a0.x += v.x; a0.y += v.y; a0.z += v.z; a0.w += v.w;
        }
        if (i1 < cnt) {
            float4 v = g_h[(size_t)g_csr[start + i1] * 4 + c];
            a1.x += v.x; a1.y += v.y; a1.z += v.z; a1.w += v.w;
        }
    }
    a0.x += a1.x; a0.y += a1.y; a0.z += a1.z; a0.w += a1.w;

    #pragma unroll
    for (int off = 16; off >= 4; off >>= 1) {
        a0.x += __shfl_xor_sync(0xffffffffu, a0.x, off);
        a0.y += __shfl_xor_sync(0xffffffffu, a0.y, off);
        a0.z += __shfl_xor_sync(0xffffffffu, a0.z, off);
        a0.w += __shfl_xor_sync(0xffffffffu, a0.w, off);
    }

    if (lane < 4) {
        float4 self = g_h[(size_t)d * 4 + lane];
        float dv = g_dinv[d];
        float4 bb = ((const float4*)b1)[lane];
        float4 r;
        r.x = fmaxf(dv * (a0.x + self.x) + bb.x, 0.f) * dv;
        r.y = fmaxf(dv * (a0.y + self.y) + bb.y, 0.f) * dv;
        r.z = fmaxf(dv * (a0.z + self.z) + bb.z, 0.f) * dv;
        r.w = fmaxf(dv * (a0.w + self.w) + bb.w, 0.f) * dv;
        g_h2[(size_t)d * 4 + lane] = r;
    }
}

// ---------------------------------------------------------------
// Pull-prop layer 2 + output epilogue (logits @ W2 + b2, softmax).
// d_out[0:N*40) = softmax ; d_out[N*40:2N*40) = logits.
__global__ __launch_bounds__(256) void k_prop2out(
    const float* __restrict__ W2, const float* __restrict__ b2,
    float* __restrict__ dout, int N, int write_h)
{
    __shared__ float w[HDIM * CDIM];
    __shared__ float bs[CDIM];
    for (int i = threadIdx.x; i < HDIM * CDIM; i += 256) w[i] = W2[i];
    if (threadIdx.x < CDIM) bs[threadIdx.x] = b2[threadIdx.x];
    __syncthreads();

    int wg = (blockIdx.x * 256 + threadIdx.x) >> 5;
    if (wg >= N) return;
    int lane = threadIdx.x & 31;
    int c = lane & 3, grp = lane >> 2;
    int d = wg;
    int start = g_rowptr[d];
    int cnt = g_deg[d];

    float4 a0 = make_float4(0.f, 0.f, 0.f, 0.f);
    float4 a1 = make_float4(0.f, 0.f, 0.f, 0.f);
    for (int base = 0; base < cnt; base += 16) {
        int i0 = base + grp, i1 = base + 8 + grp;
        if (i0 < cnt) {
            float4 v = g_h2[(size_t)g_csr[start + i0] * 4 + c];
            a0.x += v.x; a0.y += v.y; a0.z += v.z; a0.w += v.w;
        }
        if (i1 < cnt) {
            float4 v = g_h2[(size_t)g_csr[start + i1] * 4 + c];
            a1.x += v.x; a1.y += v.y; a1.z += v.z; a1.w += v.w;
        }
    }
    a0.x += a1.x; a0.y += a1.y; a0.z += a1.z; a0.w += a1.w;

    #pragma unroll
    for (int off = 16; off >= 4; off >>= 1) {
        a0.x += __shfl_xor_sync(0xffffffffu, a0.x, off);
        a0.y += __shfl_xor_sync(0xffffffffu, a0.y, off);
        a0.z += __shfl_xor_sync(0xffffffffu, a0.z, off);
        a0.w += __shfl_xor_sync(0xffffffffu, a0.w, off);
    }

    // add self + scale (every lane holds its class-c chunk)
    {
        float4 self = g_h2[(size_t)d * 4 + c];
        float dv = g_dinv[d];
        a0.x = dv * (a0.x + self.x);
        a0.y = dv * (a0.y + self.y);
        a0.z = dv * (a0.z + self.z);
        a0.w = dv * (a0.w + self.w);
    }

    // broadcast the 16-vector to all lanes (chunk q lives on lane q)
    float row[HDIM];
    #pragma unroll
    for (int q = 0; q < 4; q++) {
        row[q * 4 + 0] = __shfl_sync(0xffffffffu, a0.x, q);
        row[q * 4 + 1] = __shfl_sync(0xffffffffu, a0.y, q);
        row[q * 4 + 2] = __shfl_sync(0xffffffffu, a0.z, q);
        row[q * 4 + 3] = __shfl_sync(0xffffffffu, a0.w, q);
    }

    // logits: lane -> class j=lane, and j=32+lane for lanes 0..7
    float l0 = bs[lane];
    bool has2 = lane < (CDIM - 32);
    float l1 = has2 ? bs[32 + lane] : -1e30f;
    #pragma unroll
    for (int k = 0; k < HDIM; k++) {
        float v = row[k];
        l0 += v * w[k * CDIM + lane];
        if (has2) l1 += v * w[k * CDIM + 32 + lane];
    }

    float m = fmaxf(l0, l1);
    #pragma unroll
    for (int off = 16; off; off >>= 1)
        m = fmaxf(m, __shfl_xor_sync(0xffffffffu, m, off));
    float e0 = __expf(l0 - m);
    float e1 = has2 ? __expf(l1 - m) : 0.0f;
    float s = e0 + e1;
    #pragma unroll
    for (int off = 16; off; off >>= 1)
        s += __shfl_xor_sync(0xffffffffu, s, off);
    float inv = 1.0f / s;

    float* so = dout + (size_t)d * CDIM;
    so[lane] = e0 * inv;
    if (has2) so[32 + lane] = e1 * inv;
    if (write_h) {
        float* ho = dout + (size_t)N * CDIM + (size_t)d * CDIM;
        ho[lane] = l0;
        if (has2) ho[32 + lane] = l1;
    }
}

// ---------------------------------------------------------------
extern "C" void kernel_launch(void* const* d_in, const int* in_sizes, int n_in,
                              void* d_out, int out_size)
{
    // metadata order: x, edge_index, num_nodes, W1, b1, W2, b2
    const float* x  = (const float*)d_in[0];
    const void*  ei = d_in[1];
    const float* W1 = (const float*)d_in[3];
    const float* b1 = (const float*)d_in[4];
    const float* W2 = (const float*)d_in[5];
    const float* b2 = (const float*)d_in[6];
    float* out = (float*)d_out;

    int N = in_sizes[0] / FDIM;
    int E = in_sizes[1] / 2;
    if (N > NMAX) N = NMAX;
    if (E > EMAX) E = EMAX;
    int write_h = (out_size >= 2 * N * CDIM) ? 1 : 0;

    const int B = 256;
    int nodeWarpBlocks = (N * 32 + B - 1) / B;

    k_init<<<(N + B - 1) / B, B>>>((const int*)ei, N);
    k_deg<<<(E + B - 1) / B, B>>>(ei, E);
    k_scan<<<1, 1024>>>(N);
    k_dinv<<<(N + B - 1) / B, B>>>(N);
    k_fill<<<(E + B - 1) / B, B>>>(ei, E);

    k_gemm1<<<(N + 31) / 32, 256>>>(x, W1, N);

    k_prop1<<<nodeWarpBlocks, B>>>(b1, N);
    k_prop2out<<<nodeWarpBlocks, B>>>(W2, b2, out, N, write_h);
}

// round 5
// speedup vs baseline: 1.1974x; 1.1974x over previous
#include <cuda_runtime.h>
#include <cstdint>

// Problem constants: N=100000, F=512, H=16, C=40, E=3200000
#define NMAX 100000
#define EMAX 3200000
#define FDIM 512
#define HDIM 16
#define CDIM 40

// ---- scratch (static device globals; no allocation allowed) ----
__device__ int    g_is64;
__device__ int2   g_edge[EMAX];        // (src, dst)
__device__ int    g_deg[NMAX];
__device__ float  g_dinv[NMAX];
__device__ float  g_h[NMAX * HDIM];    // dinv-scaled hidden (gather table)
__device__ float  g_agg1[NMAX * HDIM]; // layer-1 accumulator (init = g_h)
__device__ float  g_agg2[NMAX * HDIM]; // layer-2 accumulator (init = scaled relu)

// ---- f32x2 packed-math helpers (sm_103a) ----
__device__ __forceinline__ unsigned long long f2_fma(
    unsigned long long a, unsigned long long b, unsigned long long c) {
    unsigned long long d;
    asm("fma.rn.f32x2 %0, %1, %2, %3;" : "=l"(d) : "l"(a), "l"(b), "l"(c));
    return d;
}
__device__ __forceinline__ unsigned long long f2_add(
    unsigned long long a, unsigned long long b) {
    unsigned long long d;
    asm("add.rn.f32x2 %0, %1, %2;" : "=l"(d) : "l"(a), "l"(b));
    return d;
}
__device__ __forceinline__ unsigned long long f2_mul(
    unsigned long long a, unsigned long long b) {
    unsigned long long d;
    asm("mul.rn.f32x2 %0, %1, %2;" : "=l"(d) : "l"(a), "l"(b));
    return d;
}
__device__ __forceinline__ unsigned long long f2_pack(float lo, float hi) {
    unsigned long long d;
    asm("mov.b64 %0, {%1, %2};" : "=l"(d) : "f"(lo), "f"(hi));
    return d;
}

// ---------------------------------------------------------------
// Zero degree array; thread 0 also detects int64 vs int32 edge buffer.
__global__ void k_init(const int* __restrict__ ei, int N) {
    int i = blockIdx.x * blockDim.x + threadIdx.x;
    if (i < N) g_deg[i] = 0;
    if (i == 0) {
        int any = 0;
        #pragma unroll
        for (int q = 1; q < 256; q += 2) any |= ei[q];
        g_is64 = (any == 0) ? 1 : 0;
    }
}

// Normalize edges to packed int2 and count in-degree (dst side).
__global__ __launch_bounds__(256) void k_convert(const void* __restrict__ ei, int E) {
    int e = blockIdx.x * blockDim.x + threadIdx.x;
    if (e >= E) return;
    int s, d;
    if (g_is64) {
        const long long* p = (const long long*)ei;
        s = (int)p[e];
        d = (int)p[(long long)E + e];
    } else {
        const int* p = (const int*)ei;
        s = p[e];
        d = p[E + e];
    }
    g_edge[e] = make_int2(s, d);
    atomicAdd(&g_deg[d], 1);
}

__global__ void k_dinv(int N) {
    int i = blockIdx.x * blockDim.x + threadIdx.x;
    if (i < N) g_dinv[i] = rsqrtf((float)(g_deg[i] + 1));  // +1 self-loop
}

// ---------------------------------------------------------------
// GEMM1 + scale:  g_h[i,:] = dinv[i] * (x[i,:] @ W1), dual-written to
// g_agg1 (self-loop init). Warp computes 4 rows; x loaded as float4
// (k = 4*lane + 128*i + q). W1 staged lane-major in shared so LDS.64
// is conflict-free. f32x2 accumulators; value-halving butterfly tail.
__global__ __launch_bounds__(256, 2) void k_gemm1(
    const float* __restrict__ x, const float* __restrict__ W1, int N)
{
    __shared__ unsigned long long wS[4096];
    {
        const unsigned long long* gw = (const unsigned long long*)W1;
        for (int idx = threadIdx.x; idx < 4096; idx += 256) {
            int lane_ = idx & 31;
            int q  = (idx >> 5) & 3;
            int i  = (idx >> 7) & 3;
            int j2 = idx >> 9;
            int k = 4 * lane_ + 128 * i + q;
            wS[idx] = gw[k * 8 + j2];
        }
    }
    __syncthreads();

    int warp = threadIdx.x >> 5;
    int lane = threadIdx.x & 31;
    int r0 = blockIdx.x * 32 + warp * 4;

    unsigned long long acc[4][8];
    #pragma unroll
    for (int r = 0; r < 4; r++)
        #pragma unroll
        for (int j = 0; j < 8; j++) acc[r][j] = 0ull;

    bool vr[4];
    const float4* xp[4];
    #pragma unroll
    for (int r = 0; r < 4; r++) {
        vr[r] = (r0 + r) < N;
        xp[r] = (const float4*)(x + (size_t)(vr[r] ? (r0 + r) : 0) * FDIM);
    }

    #pragma unroll
    for (int i = 0; i < 4; i++) {
        float4 xv[4];
        #pragma unroll
        for (int r = 0; r < 4; r++) {
            float4 t = xp[r][lane + 32 * i];
            xv[r].x = vr[r] ? t.x : 0.0f;
            xv[r].y = vr[r] ? t.y : 0.0f;
            xv[r].z = vr[r] ? t.z : 0.0f;
            xv[r].w = vr[r] ? t.w : 0.0f;
        }
        #pragma unroll
        for (int q = 0; q < 4; q++) {
            unsigned long long pr[4];
            #pragma unroll
            for (int r = 0; r < 4; r++) {
                float c = (q == 0) ? xv[r].x : (q == 1) ? xv[r].y
                        : (q == 2) ? xv[r].z : xv[r].w;
                pr[r] = f2_pack(c, c);
            }
            #pragma unroll
            for (int j = 0; j < 8; j++) {
                unsigned long long wv = wS[((j * 4 + i) * 4 + q) * 32 + lane];
                acc[0][j] = f2_fma(pr[0], wv, acc[0][j]);
                acc[1][j] = f2_fma(pr[1], wv, acc[1][j]);
                acc[2][j] = f2_fma(pr[2], wv, acc[2][j]);
                acc[3][j] = f2_fma(pr[3], wv, acc[3][j]);
            }
        }
    }

    // value-halving butterfly: 32 packed values -> 1 per lane
    unsigned long long v[32];
    #pragma unroll
    for (int r = 0; r < 4; r++)
        #pragma unroll
        for (int j = 0; j < 8; j++) v[r * 8 + j] = acc[r][j];

    #pragma unroll
    for (int s = 0; s < 5; s++) {
        const int m = 1 << s;
        const int half = 16 >> s;
        bool up = (lane & m) != 0;
        #pragma unroll
        for (int q = 0; q < 16; q++) {
            if (q < half) {
                unsigned long long keep = up ? v[q + half] : v[q];
                unsigned long long mine = up ? v[q] : v[q + half];
                unsigned long long got = __shfl_xor_sync(0xffffffffu, mine, m);
                v[q] = f2_add(keep, got);
            }
        }
    }

    int p = ((lane & 1) << 4) | ((lane & 2) << 2) | (lane & 4) |
            ((lane & 8) >> 2) | ((lane & 16) >> 4);
    int r = p >> 3, j2 = p & 7;
    int row = r0 + r;
    if (row < N) {
        float dv = g_dinv[row];
        unsigned long long res = f2_mul(v[0], f2_pack(dv, dv));
        size_t off = (size_t)row * 8 + j2;  // float2 index
        ((unsigned long long*)g_h)[off] = res;
        ((unsigned long long*)g_agg1)[off] = res;
    }
}

// ---------------------------------------------------------------
// Edge propagation, one thread per edge: load edge once, read the
// 64B source row (L1-served after first sector fetch), issue 4
// red.global.add.v4 into the destination row.
__global__ __launch_bounds__(256) void k_prop(int E, int layer) {
    int e = blockIdx.x * blockDim.x + threadIdx.x;
    if (e >= E) return;
    const float4* hin = (const float4*)g_h;
    float* out = layer ? g_agg2 : g_agg1;

    int2 sd = g_edge[e];
    const float4* src = hin + (size_t)sd.x * 4;
    float* p = out + (size_t)sd.y * HDIM;

    float4 v0 = src[0];
    float4 v1 = src[1];
    float4 v2 = src[2];
    float4 v3 = src[3];
    asm volatile("red.global.add.v4.f32 [%0], {%1, %2, %3, %4};"
                 :: "l"(p), "f"(v0.x), "f"(v0.y), "f"(v0.z), "f"(v0.w) : "memory");
    asm volatile("red.global.add.v4.f32 [%0], {%1, %2, %3, %4};"
                 :: "l"(p + 4), "f"(v1.x), "f"(v1.y), "f"(v1.z), "f"(v1.w) : "memory");
    asm volatile("red.global.add.v4.f32 [%0], {%1, %2, %3, %4};"
                 :: "l"(p + 8), "f"(v2.x), "f"(v2.y), "f"(v2.z), "f"(v2.w) : "memory");
    asm volatile("red.global.add.v4.f32 [%0], {%1, %2, %3, %4};"
                 :: "l"(p + 12), "f"(v3.x), "f"(v3.y), "f"(v3.z), "f"(v3.w) : "memory");
}

// ---------------------------------------------------------------
// Mid layer: out1 = relu(dinv[i]*agg1 + b1); hs2 = dinv[i]*out1
// dual-written to g_h (gather table) and g_agg2 (self-loop init).
__global__ void k_mid(const float* __restrict__ b1, int N) {
    int idx = blockIdx.x * blockDim.x + threadIdx.x;
    if (idx >= N * HDIM) return;
    int i = idx >> 4;
    float dv = g_dinv[i];
    float v = dv * g_agg1[idx] + b1[idx & 15];
    v = v > 0.0f ? v : 0.0f;
    v *= dv;
    g_h[idx] = v;
    g_agg2[idx] = v;
}

// ---------------------------------------------------------------
// Output: logits = (dinv[i]*agg2[i,:]) @ W2 + b2 ; out = softmax
// d_out[0:N*40) = softmax ; d_out[N*40:2N*40) = logits
__global__ __launch_bounds__(256) void k_out(
    const float* __restrict__ W2, const float* __restrict__ b2,
    float* __restrict__ dout, int N, int write_h)
{
    __shared__ float w[HDIM * CDIM];
    __shared__ float bs[CDIM];
    for (int i = threadIdx.x; i < HDIM * CDIM; i += blockDim.x) w[i] = W2[i];
    if (threadIdx.x < CDIM) bs[threadIdx.x] = b2[threadIdx.x];
    __syncthreads();

    int i = blockIdx.x * blockDim.x + threadIdx.x;
    if (i >= N) return;

    float dv = g_dinv[i];
    float row[HDIM];
    const float4* p = (const float4*)(g_agg2 + (size_t)i * HDIM);
    #pragma unroll
    for (int q = 0; q < 4; q++) {
        float4 v = p[q];
        row[q * 4 + 0] = v.x * dv; row[q * 4 + 1] = v.y * dv;
        row[q * 4 + 2] = v.z * dv; row[q * 4 + 3] = v.w * dv;
    }

    float logit[CDIM];
    #pragma unroll
    for (int j = 0; j < CDIM; j++) logit[j] = bs[j];
    #pragma unroll
    for (int k = 0; k < HDIM; k++) {
        float v = row[k];
        const float* wr = &w[k * CDIM];
        #pragma unroll
        for (int j = 0; j < CDIM; j++) logit[j] += v * wr[j];
    }

    float mx = logit[0];
    #pragma unroll
    for (int j = 1; j < CDIM; j++) mx = fmaxf(mx, logit[j]);
    float sum = 0.0f;
    #pragma unroll
    for (int j = 0; j < CDIM; j++) sum += __expf(logit[j] - mx);
    float inv = 1.0f / sum;

    float* so = dout + (size_t)i * CDIM;
    #pragma unroll
    for (int j = 0; j < CDIM; j++) so[j] = __expf(logit[j] - mx) * inv;

    if (write_h) {
        float* ho = dout + (size_t)N * CDIM + (size_t)i * CDIM;
        #pragma unroll
        for (int j = 0; j < CDIM; j++) ho[j] = logit[j];
    }
}

// ---------------------------------------------------------------
extern "C" void kernel_launch(void* const* d_in, const int* in_sizes, int n_in,
                              void* d_out, int out_size)
{
    // metadata order: x, edge_index, num_nodes, W1, b1, W2, b2
    const float* x  = (const float*)d_in[0];
    const void*  ei = d_in[1];
    const float* W1 = (const float*)d_in[3];
    const float* b1 = (const float*)d_in[4];
    const float* W2 = (const float*)d_in[5];
    const float* b2 = (const float*)d_in[6];
    float* out = (float*)d_out;

    int N = in_sizes[0] / FDIM;
    int E = in_sizes[1] / 2;
    if (N > NMAX) N = NMAX;
    if (E > EMAX) E = EMAX;
    int write_h = (out_size >= 2 * N * CDIM) ? 1 : 0;

    const int B = 256;

    k_init<<<(N + B - 1) / B, B>>>((const int*)ei, N);
    k_convert<<<(E + B - 1) / B, B>>>(ei, E);
    k_dinv<<<(N + B - 1) / B, B>>>(N);

    k_gemm1<<<(N + 31) / 32, 256>>>(x, W1, N);

    k_prop<<<(E + B - 1) / B, B>>>(E, 0);
    k_mid<<<(N * HDIM + B - 1) / B, B>>>(b1, N);
    k_prop<<<(E + B - 1) / B, B>>>(E, 1);

    k_out<<<(N + B - 1) / B, B>>>(W2, b2, out, N, write_h);
}

// round 6
// speedup vs baseline: 1.3807x; 1.1531x over previous
#include <cuda_runtime.h>
#include <cstdint>

// Problem constants: N=100000, F=512, H=16, C=40, E=3200000
#define NMAX 100000
#define EMAX 3200000
#define FDIM 512
#define HDIM 16
#define CDIM 40

// ---- scratch (static device globals; no allocation allowed) ----
__device__ int    g_is64;
__device__ int2   g_edge[EMAX];        // (src, dst)
__device__ int    g_deg[NMAX];
__device__ float  g_dinv[NMAX];
__device__ float  g_h[NMAX * HDIM];    // dinv-scaled hidden (gather table)
__device__ float  g_agg1[NMAX * HDIM]; // layer-1 accumulator (init = g_h)
__device__ float  g_agg2[NMAX * HDIM]; // layer-2 accumulator (init = scaled relu)

// ---- f32x2 packed-math helpers (sm_103a) ----
__device__ __forceinline__ unsigned long long f2_fma(
    unsigned long long a, unsigned long long b, unsigned long long c) {
    unsigned long long d;
    asm("fma.rn.f32x2 %0, %1, %2, %3;" : "=l"(d) : "l"(a), "l"(b), "l"(c));
    return d;
}
__device__ __forceinline__ unsigned long long f2_add(
    unsigned long long a, unsigned long long b) {
    unsigned long long d;
    asm("add.rn.f32x2 %0, %1, %2;" : "=l"(d) : "l"(a), "l"(b));
    return d;
}
__device__ __forceinline__ unsigned long long f2_mul(
    unsigned long long a, unsigned long long b) {
    unsigned long long d;
    asm("mul.rn.f32x2 %0, %1, %2;" : "=l"(d) : "l"(a), "l"(b));
    return d;
}
__device__ __forceinline__ unsigned long long f2_pack(float lo, float hi) {
    unsigned long long d;
    asm("mov.b64 %0, {%1, %2};" : "=l"(d) : "f"(lo), "f"(hi));
    return d;
}

// ---------------------------------------------------------------
// Zero degree array; thread 0 also detects int64 vs int32 edge buffer.
__global__ void k_init(const int* __restrict__ ei, int N) {
    int i = blockIdx.x * blockDim.x + threadIdx.x;
    if (i < N) g_deg[i] = 0;
    if (i == 0) {
        int any = 0;
        #pragma unroll
        for (int q = 1; q < 256; q += 2) any |= ei[q];
        g_is64 = (any == 0) ? 1 : 0;
    }
}

// Normalize edges to packed int2 and count in-degree (dst side).
__global__ __launch_bounds__(256) void k_convert(const void* __restrict__ ei, int E) {
    int e = blockIdx.x * blockDim.x + threadIdx.x;
    if (e >= E) return;
    int s, d;
    if (g_is64) {
        const long long* p = (const long long*)ei;
        s = (int)p[e];
        d = (int)p[(long long)E + e];
    } else {
        const int* p = (const int*)ei;
        s = p[e];
        d = p[E + e];
    }
    g_edge[e] = make_int2(s, d);
    atomicAdd(&g_deg[d], 1);
}

__global__ void k_dinv(int N) {
    int i = blockIdx.x * blockDim.x + threadIdx.x;
    if (i < N) g_dinv[i] = rsqrtf((float)(g_deg[i] + 1));  // +1 self-loop
}

// ---------------------------------------------------------------
// GEMM1 + scale epilogue:  hs[i,:] = dinv[i] * (x[i,:] @ W1)
// dual-written to g_h (gather table) and g_agg1 (self-loop init).
//
// Block = 256 threads = 8 warps; warp computes 4 rows; k split across
// lanes (k = lane + 32*i), scalar coalesced x loads. Accumulators are
// f32x2-packed j-pairs. W1 staged in shared as float2 j-pairs with odd
// pitch -> LDS.64 conflict-free. Cross-lane reduction: value-halving
// butterfly done IN PLACE on acc (no second register array) so regs
// stay under the launch_bounds(256,3) cap (>= 24 warps/SM).
#define WPITCH 513
__global__ __launch_bounds__(256, 3) void k_gemm1(
    const float* __restrict__ x, const float* __restrict__ W1, int N)
{
    __shared__ unsigned long long wS[8 * WPITCH];

    // stage W1: float2 element idx = k*8 + j2  (W1 row-major [512][16])
    {
        const unsigned long long* gw = (const unsigned long long*)W1;
        for (int idx = threadIdx.x; idx < FDIM * 8; idx += 256) {
            int k = idx >> 3, j2 = idx & 7;
            wS[j2 * WPITCH + k] = gw[idx];
        }
    }
    __syncthreads();

    int warp = threadIdx.x >> 5;
    int lane = threadIdx.x & 31;
    int r0 = blockIdx.x * 32 + warp * 4;

    // flat accumulator: acc[r*8 + j2]
    unsigned long long acc[32];
    #pragma unroll
    for (int q = 0; q < 32; q++) acc[q] = 0ull;

    bool v0 = (r0 + 0) < N, v1 = (r0 + 1) < N, v2 = (r0 + 2) < N, v3 = (r0 + 3) < N;
    const float* x0p = x + (size_t)(r0 + 0) * FDIM + lane;
    const float* x1p = x + (size_t)(r0 + 1) * FDIM + lane;
    const float* x2p = x + (size_t)(r0 + 2) * FDIM + lane;
    const float* x3p = x + (size_t)(r0 + 3) * FDIM + lane;

    #pragma unroll 4
    for (int i = 0; i < 16; i++) {
        int k = lane + 32 * i;
        float x0 = v0 ? x0p[32 * i] : 0.0f;
        float x1 = v1 ? x1p[32 * i] : 0.0f;
        float x2 = v2 ? x2p[32 * i] : 0.0f;
        float x3 = v3 ? x3p[32 * i] : 0.0f;
        unsigned long long p0 = f2_pack(x0, x0);
        unsigned long long p1 = f2_pack(x1, x1);
        unsigned long long p2 = f2_pack(x2, x2);
        unsigned long long p3 = f2_pack(x3, x3);
        #pragma unroll
        for (int j = 0; j < 8; j++) {
            unsigned long long wv = wS[j * WPITCH + k];
            acc[0 * 8 + j] = f2_fma(p0, wv, acc[0 * 8 + j]);
            acc[1 * 8 + j] = f2_fma(p1, wv, acc[1 * 8 + j]);
            acc[2 * 8 + j] = f2_fma(p2, wv, acc[2 * 8 + j]);
            acc[3 * 8 + j] = f2_fma(p3, wv, acc[3 * 8 + j]);
        }
    }

    // value-halving butterfly IN PLACE: 32 packed values -> 1 per lane.
    #pragma unroll
    for (int s = 0; s < 5; s++) {
        const int m = 1 << s;          // xor mask this round
        const int half = 16 >> s;      // values kept after this round
        bool up = (lane & m) != 0;
        #pragma unroll
        for (int q = 0; q < 16; q++) { // constant trip count; guard by half
            if (q < half) {
                unsigned long long keep = up ? acc[q + half] : acc[q];
                unsigned long long mine = up ? acc[q] : acc[q + half];
                unsigned long long got = __shfl_xor_sync(0xffffffffu, mine, m);
                acc[q] = f2_add(keep, got);
            }
        }
    }

    // p = bitrev5(lane): round m=1 fixed bit4 ... m=16 fixed bit0
    int p = ((lane & 1) << 4) | ((lane & 2) << 2) | (lane & 4) |
            ((lane & 8) >> 2) | ((lane & 16) >> 4);
    int r = p >> 3, j2 = p & 7;
    int row = r0 + r;
    if (row < N) {
        float dv = g_dinv[row];
        unsigned long long res = f2_mul(acc[0], f2_pack(dv, dv));
        size_t off = (size_t)row * 8 + j2;  // float2 index
        ((unsigned long long*)g_h)[off] = res;
        ((unsigned long long*)g_agg1)[off] = res;
    }
}

// ---------------------------------------------------------------
// Edge propagation: 4 threads per edge, one float4 chunk each.
__global__ __launch_bounds__(256) void k_prop(int E, int layer) {
    int t = blockIdx.x * blockDim.x + threadIdx.x;
    int e = t >> 2;
    if (e >= E) return;
    int c = t & 3;
    const float4* hin = (const float4*)g_h;
    float* out = layer ? g_agg2 : g_agg1;

    int2 sd = g_edge[e];
    float4 v = hin[(size_t)sd.x * 4 + c];
    float* p = out + (size_t)sd.y * HDIM + c * 4;
    asm volatile("red.global.add.v4.f32 [%0], {%1, %2, %3, %4};"
                 :: "l"(p), "f"(v.x), "f"(v.y), "f"(v.z), "f"(v.w)
                 : "memory");
}

// ---------------------------------------------------------------
// Mid layer: out1 = relu(dinv[i]*agg1 + b1); hs2 = dinv[i]*out1
__global__ void k_mid(const float* __restrict__ b1, int N) {
    int idx = blockIdx.x * blockDim.x + threadIdx.x;
    if (idx >= N * HDIM) return;
    int i = idx >> 4;
    float dv = g_dinv[i];
    float v = dv * g_agg1[idx] + b1[idx & 15];
    v = v > 0.0f ? v : 0.0f;
    v *= dv;
    g_h[idx] = v;
    g_agg2[idx] = v;
}

// ---------------------------------------------------------------
// Output: logits = (dinv[i]*agg2[i,:]) @ W2 + b2 ; out = softmax
__global__ __launch_bounds__(256) void k_out(
    const float* __restrict__ W2, const float* __restrict__ b2,
    float* __restrict__ dout, int N, int write_h)
{
    __shared__ float w[HDIM * CDIM];
    __shared__ float bs[CDIM];
    for (int i = threadIdx.x; i < HDIM * CDIM; i += blockDim.x) w[i] = W2[i];
    if (threadIdx.x < CDIM) bs[threadIdx.x] = b2[threadIdx.x];
    __syncthreads();

    int i = blockIdx.x * blockDim.x + threadIdx.x;
    if (i >= N) return;

    float dv = g_dinv[i];
    float row[HDIM];
    const float4* p = (const float4*)(g_agg2 + (size_t)i * HDIM);
    #pragma unroll
    for (int q = 0; q < 4; q++) {
        float4 v = p[q];
        row[q * 4 + 0] = v.x * dv; row[q * 4 + 1] = v.y * dv;
        row[q * 4 + 2] = v.z * dv; row[q * 4 + 3] = v.w * dv;
    }

    float logit[CDIM];
    #pragma unroll
    for (int j = 0; j < CDIM; j++) logit[j] = bs[j];
    #pragma unroll
    for (int k = 0; k < HDIM; k++) {
        float v = row[k];
        const float* wr = &w[k * CDIM];
        #pragma unroll
        for (int j = 0; j < CDIM; j++) logit[j] += v * wr[j];
    }

    float mx = logit[0];
    #pragma unroll
    for (int j = 1; j < CDIM; j++) mx = fmaxf(mx, logit[j]);
    float sum = 0.0f;
    #pragma unroll
    for (int j = 0; j < CDIM; j++) sum += __expf(logit[j] - mx);
    float inv = 1.0f / sum;

    float* so = dout + (size_t)i * CDIM;
    #pragma unroll
    for (int j = 0; j < CDIM; j++) so[j] = __expf(logit[j] - mx) * inv;

    if (write_h) {
        float* ho = dout + (size_t)N * CDIM + (size_t)i * CDIM;
        #pragma unroll
        for (int j = 0; j < CDIM; j++) ho[j] = logit[j];
    }
}

// ---------------------------------------------------------------
extern "C" void kernel_launch(void* const* d_in, const int* in_sizes, int n_in,
                              void* d_out, int out_size)
{
    // metadata order: x, edge_index, num_nodes, W1, b1, W2, b2
    const float* x  = (const float*)d_in[0];
    const void*  ei = d_in[1];
    const float* W1 = (const float*)d_in[3];
    const float* b1 = (const float*)d_in[4];
    const float* W2 = (const float*)d_in[5];
    const float* b2 = (const float*)d_in[6];
    float* out = (float*)d_out;

    int N = in_sizes[0] / FDIM;
    int E = in_sizes[1] / 2;
    if (N > NMAX) N = NMAX;
    if (E > EMAX) E = EMAX;
    int write_h = (out_size >= 2 * N * CDIM) ? 1 : 0;

    const int B = 256;

    k_init<<<(N + B - 1) / B, B>>>((const int*)ei, N);
    k_convert<<<(E + B - 1) / B, B>>>(ei, E);
    k_dinv<<<(N + B - 1) / B, B>>>(N);

    k_gemm1<<<(N + 31) / 32, 256>>>(x, W1, N);

    k_prop<<<((size_t)E * 4 + B - 1) / B, B>>>(E, 0);
    k_mid<<<(N * HDIM + B - 1) / B, B>>>(b1, N);
    k_prop<<<((size_t)E * 4 + B - 1) / B, B>>>(E, 1);

    k_out<<<(N + B - 1) / B, B>>>(W2, b2, out, N, write_h);
}

// round 7
// speedup vs baseline: 1.6117x; 1.1674x over previous
#include <cuda_runtime.h>
#include <cuda_fp16.h>
#include <cstdint>

// Problem constants: N=100000, F=512, H=16, C=40, E=3200000
#define NMAX 100000
#define EMAX 3200000
#define FDIM 512
#define HDIM 16
#define CDIM 40

// ---- scratch (static device globals; no allocation allowed) ----
__device__ int     g_is64;
__device__ int2    g_edge[EMAX];        // (src, dst)
__device__ int     g_deg[NMAX];
__device__ float   g_dinv[NMAX];
__device__ __half2 g_h[NMAX * 8];       // dinv-scaled hidden, fp16 gather table
__device__ float   g_agg1[NMAX * HDIM]; // layer-1 accumulator (init = scaled h1)
__device__ float   g_agg2[NMAX * HDIM]; // layer-2 accumulator (init = scaled relu)

// ---- f32x2 packed-math helpers (sm_103a) ----
__device__ __forceinline__ unsigned long long f2_fma(
    unsigned long long a, unsigned long long b, unsigned long long c) {
    unsigned long long d;
    asm("fma.rn.f32x2 %0, %1, %2, %3;" : "=l"(d) : "l"(a), "l"(b), "l"(c));
    return d;
}
__device__ __forceinline__ unsigned long long f2_add(
    unsigned long long a, unsigned long long b) {
    unsigned long long d;
    asm("add.rn.f32x2 %0, %1, %2;" : "=l"(d) : "l"(a), "l"(b));
    return d;
}
__device__ __forceinline__ unsigned long long f2_mul(
    unsigned long long a, unsigned long long b) {
    unsigned long long d;
    asm("mul.rn.f32x2 %0, %1, %2;" : "=l"(d) : "l"(a), "l"(b));
    return d;
}
__device__ __forceinline__ unsigned long long f2_pack(float lo, float hi) {
    unsigned long long d;
    asm("mov.b64 %0, {%1, %2};" : "=l"(d) : "f"(lo), "f"(hi));
    return d;
}

// ---------------------------------------------------------------
// Zero degree array; thread 0 also detects int64 vs int32 edge buffer.
__global__ void k_init(const int* __restrict__ ei, int N) {
    int i = blockIdx.x * blockDim.x + threadIdx.x;
    if (i < N) g_deg[i] = 0;
    if (i == 0) {
        int any = 0;
        #pragma unroll
        for (int q = 1; q < 256; q += 2) any |= ei[q];
        g_is64 = (any == 0) ? 1 : 0;
    }
}

// Normalize edges to packed int2 and count in-degree (dst side).
__global__ __launch_bounds__(256) void k_convert(const void* __restrict__ ei, int E) {
    int e = blockIdx.x * blockDim.x + threadIdx.x;
    if (e >= E) return;
    int s, d;
    if (g_is64) {
        const long long* p = (const long long*)ei;
        s = (int)p[e];
        d = (int)p[(long long)E + e];
    } else {
        const int* p = (const int*)ei;
        s = p[e];
        d = p[E + e];
    }
    g_edge[e] = make_int2(s, d);
    atomicAdd(&g_deg[d], 1);
}

__global__ void k_dinv(int N) {
    int i = blockIdx.x * blockDim.x + threadIdx.x;
    if (i < N) g_dinv[i] = rsqrtf((float)(g_deg[i] + 1));  // +1 self-loop
}

// ---------------------------------------------------------------
// GEMM1 + scale epilogue:  hs[i,:] = dinv[i] * (x[i,:] @ W1)
// written to g_h (fp16 gather table) and g_agg1 (fp32 self-loop init).
// Exact R3 structure: 8 warps/block, warp computes 4 rows, scalar
// coalesced x loads (k = lane + 32*i), f32x2 accumulators, W1 in
// shared as float2 j-pairs with odd pitch, value-halving butterfly
// reduction into bit-reversed lane index.
#define WPITCH 513
__global__ __launch_bounds__(256, 2) void k_gemm1(
    const float* __restrict__ x, const float* __restrict__ W1, int N)
{
    __shared__ unsigned long long wS[8 * WPITCH];

    // stage W1: float2 element idx = k*8 + j2  (W1 row-major [512][16])
    {
        const unsigned long long* gw = (const unsigned long long*)W1;
        for (int idx = threadIdx.x; idx < FDIM * 8; idx += 256) {
            int k = idx >> 3, j2 = idx & 7;
            wS[j2 * WPITCH + k] = gw[idx];
        }
    }
    __syncthreads();

    int warp = threadIdx.x >> 5;
    int lane = threadIdx.x & 31;
    int r0 = blockIdx.x * 32 + warp * 4;

    unsigned long long acc[4][8];
    #pragma unroll
    for (int r = 0; r < 4; r++)
        #pragma unroll
        for (int j = 0; j < 8; j++) acc[r][j] = 0ull;

    bool v0 = (r0 + 0) < N, v1 = (r0 + 1) < N, v2 = (r0 + 2) < N, v3 = (r0 + 3) < N;
    const float* x0p = x + (size_t)(r0 + 0) * FDIM + lane;
    const float* x1p = x + (size_t)(r0 + 1) * FDIM + lane;
    const float* x2p = x + (size_t)(r0 + 2) * FDIM + lane;
    const float* x3p = x + (size_t)(r0 + 3) * FDIM + lane;

    #pragma unroll 4
    for (int i = 0; i < 16; i++) {
        int k = lane + 32 * i;
        float x0 = v0 ? x0p[32 * i] : 0.0f;
        float x1 = v1 ? x1p[32 * i] : 0.0f;
        float x2 = v2 ? x2p[32 * i] : 0.0f;
        float x3 = v3 ? x3p[32 * i] : 0.0f;
        unsigned long long p0 = f2_pack(x0, x0);
        unsigned long long p1 = f2_pack(x1, x1);
        unsigned long long p2 = f2_pack(x2, x2);
        unsigned long long p3 = f2_pack(x3, x3);
        #pragma unroll
        for (int j = 0; j < 8; j++) {
            unsigned long long wv = wS[j * WPITCH + k];
            acc[0][j] = f2_fma(p0, wv, acc[0][j]);
            acc[1][j] = f2_fma(p1, wv, acc[1][j]);
            acc[2][j] = f2_fma(p2, wv, acc[2][j]);
            acc[3][j] = f2_fma(p3, wv, acc[3][j]);
        }
    }

    // value-halving butterfly: 32 packed values -> 1 per lane.
    unsigned long long v[32];
    #pragma unroll
    for (int r = 0; r < 4; r++)
        #pragma unroll
        for (int j = 0; j < 8; j++) v[r * 8 + j] = acc[r][j];

    #pragma unroll
    for (int s = 0; s < 5; s++) {
        const int m = 1 << s;
        const int half = 16 >> s;
        bool up = (lane & m) != 0;
        #pragma unroll
        for (int q = 0; q < 16; q++) {
            if (q < half) {
                unsigned long long keep = up ? v[q + half] : v[q];
                unsigned long long mine = up ? v[q] : v[q + half];
                unsigned long long got = __shfl_xor_sync(0xffffffffu, mine, m);
                v[q] = f2_add(keep, got);
            }
        }
    }

    int p = ((lane & 1) << 4) | ((lane & 2) << 2) | (lane & 4) |
            ((lane & 8) >> 2) | ((lane & 16) >> 4);
    int r = p >> 3, j2 = p & 7;
    int row = r0 + r;
    if (row < N) {
        float dv = g_dinv[row];
        unsigned long long res = f2_mul(v[0], f2_pack(dv, dv));
        size_t off = (size_t)row * 8 + j2;  // float2 index
        ((unsigned long long*)g_agg1)[off] = res;
        float2 rf = *(float2*)&res;
        g_h[off] = __float22half2_rn(rf);
    }
}

// ---------------------------------------------------------------
// Edge propagation: 4 threads per edge, one 4-half chunk each (8B).
// agg[dst] += h16[src] (converted to fp32; RED stays fp32).
__global__ __launch_bounds__(256) void k_prop(int E, int layer) {
    int t = blockIdx.x * blockDim.x + threadIdx.x;
    int e = t >> 2;
    if (e >= E) return;
    int c = t & 3;
    const uint2* hin = (const uint2*)g_h;   // 8B = 4 halves per chunk
    float* out = layer ? g_agg2 : g_agg1;

    int2 sd = g_edge[e];
    uint2 hv = hin[(size_t)sd.x * 4 + c];
    __half2 ha = *(__half2*)&hv.x;
    __half2 hb = *(__half2*)&hv.y;
    float2 f0 = __half22float2(ha);
    float2 f1 = __half22float2(hb);
    float* p = out + (size_t)sd.y * HDIM + c * 4;
    asm volatile("red.global.add.v4.f32 [%0], {%1, %2, %3, %4};"
                 :: "l"(p), "f"(f0.x), "f"(f0.y), "f"(f1.x), "f"(f1.y)
                 : "memory");
}

// ---------------------------------------------------------------
// Mid layer (per j-pair): out1 = relu(dinv*agg1 + b1); hs2 = dinv*out1
// writes g_h (fp16) and g_agg2 (fp32 self-loop init).
__global__ void k_mid(const float* __restrict__ b1, int N) {
    int idx = blockIdx.x * blockDim.x + threadIdx.x;   // pair index
    if (idx >= N * 8) return;
    int i = idx >> 3;
    int j2 = idx & 7;
    float dv = g_dinv[i];
    float2 a = ((const float2*)g_agg1)[idx];
    float2 bb = ((const float2*)b1)[j2];
    float2 r;
    r.x = fmaxf(dv * a.x + bb.x, 0.0f) * dv;
    r.y = fmaxf(dv * a.y + bb.y, 0.0f) * dv;
    g_h[idx] = __float22half2_rn(r);
    ((float2*)g_agg2)[idx] = r;
}

// ---------------------------------------------------------------
// Output: logits = (dinv[i]*agg2[i,:]) @ W2 + b2 ; out = softmax
// d_out[0:N*40) = softmax ; d_out[N*40:2N*40) = logits
__global__ __launch_bounds__(256) void k_out(
    const float* __restrict__ W2, const float* __restrict__ b2,
    float* __restrict__ dout, int N, int write_h)
{
    __shared__ float w[HDIM * CDIM];
    __shared__ float bs[CDIM];
    for (int i = threadIdx.x; i < HDIM * CDIM; i += blockDim.x) w[i] = W2[i];
    if (threadIdx.x < CDIM) bs[threadIdx.x] = b2[threadIdx.x];
    __syncthreads();

    int i = blockIdx.x * blockDim.x + threadIdx.x;
    if (i >= N) return;

    float dv = g_dinv[i];
    float row[HDIM];
    const float4* p = (const float4*)(g_agg2 + (size_t)i * HDIM);
    #pragma unroll
    for (int q = 0; q < 4; q++) {
        float4 v = p[q];
        row[q * 4 + 0] = v.x * dv; row[q * 4 + 1] = v.y * dv;
        row[q * 4 + 2] = v.z * dv; row[q * 4 + 3] = v.w * dv;
    }

    float logit[CDIM];
    #pragma unroll
    for (int j = 0; j < CDIM; j++) logit[j] = bs[j];
    #pragma unroll
    for (int k = 0; k < HDIM; k++) {
        float v = row[k];
        const float* wr = &w[k * CDIM];
        #pragma unroll
        for (int j = 0; j < CDIM; j++) logit[j] += v * wr[j];
    }

    float mx = logit[0];
    #pragma unroll
    for (int j = 1; j < CDIM; j++) mx = fmaxf(mx, logit[j]);
    float sum = 0.0f;
    #pragma unroll
    for (int j = 0; j < CDIM; j++) sum += __expf(logit[j] - mx);
    float inv = 1.0f / sum;

    float* so = dout + (size_t)i * CDIM;
    #pragma unroll
    for (int j = 0; j < CDIM; j++) so[j] = __expf(logit[j] - mx) * inv;

    if (write_h) {
        float* ho = dout + (size_t)N * CDIM + (size_t)i * CDIM;
        #pragma unroll
        for (int j = 0; j < CDIM; j++) ho[j] = logit[j];
    }
}

// ---------------------------------------------------------------
extern "C" void kernel_launch(void* const* d_in, const int* in_sizes, int n_in,
                              void* d_out, int out_size)
{
    // metadata order: x, edge_index, num_nodes, W1, b1, W2, b2
    const float* x  = (const float*)d_in[0];
    const void*  ei = d_in[1];
    const float* W1 = (const float*)d_in[3];
    const float* b1 = (const float*)d_in[4];
    const float* W2 = (const float*)d_in[5];
    const float* b2 = (const float*)d_in[6];
    float* out = (float*)d_out;

    int N = in_sizes[0] / FDIM;
    int E = in_sizes[1] / 2;
    if (N > NMAX) N = NMAX;
    if (E > EMAX) E = EMAX;
    int write_h = (out_size >= 2 * N * CDIM) ? 1 : 0;

    const int B = 256;

    k_init<<<(N + B - 1) / B, B>>>((const int*)ei, N);
    k_convert<<<(E + B - 1) / B, B>>>(ei, E);
    k_dinv<<<(N + B - 1) / B, B>>>(N);

    k_gemm1<<<(N + 31) / 32, 256>>>(x, W1, N);

    k_prop<<<((size_t)E * 4 + B - 1) / B, B>>>(E, 0);
    k_mid<<<(N * 8 + B - 1) / B, B>>>(b1, N);
    k_prop<<<((size_t)E * 4 + B - 1) / B, B>>>(E, 1);

    k_out<<<(N + B - 1) / B, B>>>(W2, b2, out, N, write_h);
}